// round 14
// baseline (speedup 1.0000x reference)
#include <cuda_runtime.h>

// FFTLayer: out = Re(FFT_512(x * window)) for 65536 rows of 512 fp32.
//
// Strategy:
//  - Pack two real rows (a,b) into one complex sequence z = a + i*b.
//  - 512-point complex FFT = 3 radix-8 Stockham stages, 64 threads/FFT,
//    registers + 2 shared-memory transposes (padded, ~conflict-free).
//  - Split: Re A[m] = (Re Z[m] + Re Z[512-m])/2, Re B[m] = (Im Z[m] + Im Z[512-m])/2.
//  - Re(FFT(real)) is even-symmetric: compute m=0..256, mirror to 257..511.
//  - Twiddles: ONE __sincosf per thread per stage, powers by chained complex
//    multiply (avoids the 0.5 instr/cyc/SM MUFU bottleneck).

#define FFT_N      512
#define T64        64              // threads per FFT
#define FPB        4               // FFTs per block
#define NTHREADS   (T64 * FPB)     // 256
#define SPAD(v)    ((v) + ((v) >> 3))   // pad every 8 entries
#define SBUF       (FFT_N + (FFT_N >> 3))  // 576 float2 per FFT

__device__ __forceinline__ float2 cadd(float2 a, float2 b) { return make_float2(a.x + b.x, a.y + b.y); }
__device__ __forceinline__ float2 csub(float2 a, float2 b) { return make_float2(a.x - b.x, a.y - b.y); }
__device__ __forceinline__ float2 cmul(float2 a, float2 b) {
    return make_float2(fmaf(a.x, b.x, -a.y * b.y), fmaf(a.x, b.y, a.y * b.x));
}
__device__ __forceinline__ float2 cmnegi(float2 a) { return make_float2(a.y, -a.x); }  // a * (-i)

// In-place 8-point DFT (forward, omega = e^{-2*pi*i/8}).
__device__ __forceinline__ void bfly8(float2* v) {
    float2 e0 = v[0], e1 = v[2], e2 = v[4], e3 = v[6];
    float2 o0 = v[1], o1 = v[3], o2 = v[5], o3 = v[7];

    // DFT4 on even samples
    float2 t0 = cadd(e0, e2), t1 = csub(e0, e2);
    float2 t2 = cadd(e1, e3), t3 = cmnegi(csub(e1, e3));
    float2 E0 = cadd(t0, t2), E2 = csub(t0, t2);
    float2 E1 = cadd(t1, t3), E3 = csub(t1, t3);

    // DFT4 on odd samples
    t0 = cadd(o0, o2); t1 = csub(o0, o2);
    t2 = cadd(o1, o3); t3 = cmnegi(csub(o1, o3));
    float2 O0 = cadd(t0, t2), O2 = csub(t0, t2);
    float2 O1 = cadd(t1, t3), O3 = csub(t1, t3);

    const float r = 0.70710678118654752440f;  // sqrt(2)/2
    float2 O1w = make_float2(r * (O1.x + O1.y), r * (O1.y - O1.x));   // * w8^1
    float2 O2w = make_float2(O2.y, -O2.x);                            // * w8^2 = -i
    float2 O3w = make_float2(r * (O3.y - O3.x), -r * (O3.x + O3.y));  // * w8^3

    v[0] = cadd(E0, O0);  v[4] = csub(E0, O0);
    v[1] = cadd(E1, O1w); v[5] = csub(E1, O1w);
    v[2] = cadd(E2, O2w); v[6] = csub(E2, O2w);
    v[3] = cadd(E3, O3w); v[7] = csub(E3, O3w);
}

// Apply v[k] *= e^{i*theta*k} for k=1..7 using one sincos + chained cmul.
__device__ __forceinline__ void twiddle8(float2* v, float theta) {
    float s, c;
    __sincosf(theta, &s, &c);
    float2 w  = make_float2(c, s);
    float2 wk = w;
    v[1] = cmul(v[1], wk);
    #pragma unroll
    for (int k = 2; k < 8; k++) {
        wk   = cmul(wk, w);
        v[k] = cmul(v[k], wk);
    }
}

__global__ void __launch_bounds__(NTHREADS)
fft512_real_kernel(const float* __restrict__ x, const float* __restrict__ win,
                   float* __restrict__ out) {
    __shared__ float2 sm[FPB][SBUF];

    const int lf = threadIdx.x >> 6;        // FFT slot within block
    const int t  = threadIdx.x & 63;        // thread within FFT (0..63)
    const int f  = blockIdx.x * FPB + lf;   // global FFT index (= 2 rows)

    const float* __restrict__ A = x + (size_t)(2 * f) * FFT_N;
    const float* __restrict__ B = A + FFT_N;
    float2* s = sm[lf];

    float2 v[8];
    // Load + window: z[n] = (a[n] + i*b[n]) * win[n], n = t + 64j
    #pragma unroll
    for (int j = 0; j < 8; j++) {
        int n  = t + 64 * j;
        float w = __ldg(win + n);
        v[j] = make_float2(__ldg(A + n) * w, __ldg(B + n) * w);
    }

    // ---- Stage 1: radix-8, n=512, s=1 (p = t) ----
    bfly8(v);
    twiddle8(v, (-6.283185307179586476f / 512.0f) * (float)t);
    #pragma unroll
    for (int k = 0; k < 8; k++) s[SPAD(8 * t + k)] = v[k];
    __syncthreads();
    #pragma unroll
    for (int j = 0; j < 8; j++) v[j] = s[SPAD(t + 64 * j)];

    // ---- Stage 2: radix-8, n=64, s=8 (p = t>>3, q = t&7) ----
    bfly8(v);
    const int p = t >> 3, q = t & 7;
    twiddle8(v, (-6.283185307179586476f / 64.0f) * (float)p);
    __syncthreads();  // WAR: all reads of exchange-1 done before overwrite
    #pragma unroll
    for (int k = 0; k < 8; k++) s[SPAD(q + 64 * p + 8 * k)] = v[k];
    __syncthreads();
    #pragma unroll
    for (int j = 0; j < 8; j++) v[j] = s[SPAD(t + 64 * j)];

    // ---- Stage 3: radix-8, n=8, s=64 (no twiddle) ----
    bfly8(v);
    __syncthreads();  // WAR before final buffer reuse
    #pragma unroll
    for (int k = 0; k < 8; k++) s[SPAD(t + 64 * k)] = v[k];  // Z[t + 64k], natural order
    __syncthreads();

    // ---- Split packed transform + exploit even symmetry of Re(FFT(real)) ----
    float* __restrict__ outA = out + (size_t)(2 * f) * FFT_N;
    float* __restrict__ outB = outA + FFT_N;
    for (int m = t; m <= 256; m += 64) {
        int mm = (FFT_N - m) & (FFT_N - 1);
        float2 zm  = s[SPAD(m)];
        float2 zmm = s[SPAD(mm)];
        float ra = 0.5f * (zm.x + zmm.x);   // Re A[m]
        float rb = 0.5f * (zm.y + zmm.y);   // Re B[m]
        outA[m] = ra;
        outB[m] = rb;
        if (m != 0 && m != 256) {           // mirror: Re spectrum of real input is even
            outA[FFT_N - m] = ra;
            outB[FFT_N - m] = rb;
        }
    }
}

extern "C" void kernel_launch(void* const* d_in, const int* in_sizes, int n_in,
                              void* d_out, int out_size) {
    const float* x   = (const float*)d_in[0];   // (256,256,512) fp32
    const float* win = (const float*)d_in[1];   // (512,) fp32
    float* out = (float*)d_out;                 // (256,256,512,1) fp32

    int rows   = in_sizes[0] / FFT_N;           // 65536
    int nffts  = rows >> 1;                     // 32768 (2 rows per FFT)
    int blocks = nffts / FPB;                   // 8192

    fft512_real_kernel<<<blocks, NTHREADS>>>(x, win, out);
}

// round 15
// speedup vs baseline: 1.3268x; 1.3268x over previous
#include <cuda_runtime.h>

// FFTLayer: out = Re(FFT_512(x * window)) for 65536 rows of 512 fp32.
//
// One FFT per WARP: 32 threads x 16 complex registers.
// 512 = 16 (regs, radix-16) x 2 (lanes, shfl.xor 16) x 16 (regs, radix-16)
// with a single XOR-swizzled shared-memory exchange in the middle and a
// shuffle-based Hermitian split at the end (no output staging pass).
//
// Packing: two real rows a,b -> z = a + i*b; Re FFT(a)[m] = (ReZ[m]+ReZ[-m])/2,
//          Re FFT(b)[m] = (ImZ[m]+ImZ[-m])/2.

#define FULLM 0xffffffffu

__device__ __forceinline__ float2 cadd(float2 a, float2 b) { return make_float2(a.x + b.x, a.y + b.y); }
__device__ __forceinline__ float2 csub(float2 a, float2 b) { return make_float2(a.x - b.x, a.y - b.y); }
__device__ __forceinline__ float2 cmul(float2 a, float2 b) {
    return make_float2(fmaf(a.x, b.x, -a.y * b.y), fmaf(a.x, b.y, a.y * b.x));
}
__device__ __forceinline__ float2 cmnegi(float2 a) { return make_float2(a.y, -a.x); }  // a * (-i)

// In-place natural-order 8-point forward DFT (validated in previous kernel).
__device__ __forceinline__ void bfly8(float2* v) {
    float2 e0 = v[0], e1 = v[2], e2 = v[4], e3 = v[6];
    float2 o0 = v[1], o1 = v[3], o2 = v[5], o3 = v[7];

    float2 t0 = cadd(e0, e2), t1 = csub(e0, e2);
    float2 t2 = cadd(e1, e3), t3 = cmnegi(csub(e1, e3));
    float2 E0 = cadd(t0, t2), E2 = csub(t0, t2);
    float2 E1 = cadd(t1, t3), E3 = csub(t1, t3);

    t0 = cadd(o0, o2); t1 = csub(o0, o2);
    t2 = cadd(o1, o3); t3 = cmnegi(csub(o1, o3));
    float2 O0 = cadd(t0, t2), O2 = csub(t0, t2);
    float2 O1 = cadd(t1, t3), O3 = csub(t1, t3);

    const float r = 0.70710678118654752440f;
    float2 O1w = make_float2(r * (O1.x + O1.y), r * (O1.y - O1.x));   // * w8^1
    float2 O2w = make_float2(O2.y, -O2.x);                            // * w8^2
    float2 O3w = make_float2(r * (O3.y - O3.x), -r * (O3.x + O3.y));  // * w8^3

    v[0] = cadd(E0, O0);  v[4] = csub(E0, O0);
    v[1] = cadd(E1, O1w); v[5] = csub(E1, O1w);
    v[2] = cadd(E2, O2w); v[6] = csub(E2, O2w);
    v[3] = cadd(E3, O3w); v[7] = csub(E3, O3w);
}

// In-place natural-order 16-point forward DFT:
//   X[2k]   = FFT8(x[n] + x[n+8])[k]
//   X[2k+1] = FFT8((x[n] - x[n+8]) * W16^n)[k]
__device__ __forceinline__ void fft16(float2* x) {
    float2 a[8], d[8];
    #pragma unroll
    for (int n = 0; n < 8; n++) { a[n] = cadd(x[n], x[n + 8]); d[n] = csub(x[n], x[n + 8]); }

    const float C1 = 0.92387953251128675613f;   // cos(pi/8)
    const float S1 = 0.38268343236508977173f;   // sin(pi/8)
    const float R  = 0.70710678118654752440f;

    d[1] = cmul(d[1], make_float2( C1, -S1));
    { float2 t = d[2]; d[2] = make_float2(R * (t.x + t.y),  R * (t.y - t.x)); }   // * (R,-R)
    d[3] = cmul(d[3], make_float2( S1, -C1));
    { float2 t = d[4]; d[4] = make_float2(t.y, -t.x); }                           // * (0,-1)
    d[5] = cmul(d[5], make_float2(-S1, -C1));
    { float2 t = d[6]; d[6] = make_float2(R * (t.y - t.x), -R * (t.x + t.y)); }   // * (-R,-R)
    d[7] = cmul(d[7], make_float2(-C1, -S1));

    bfly8(a); bfly8(d);
    #pragma unroll
    for (int k = 0; k < 8; k++) { x[2 * k] = a[k]; x[2 * k + 1] = d[k]; }
}

#define WARPS_PER_BLOCK 4
#define NTHREADS (32 * WARPS_PER_BLOCK)

__global__ void __launch_bounds__(NTHREADS, 5)
fft512_warp_kernel(const float* __restrict__ x, const float* __restrict__ win,
                   float* __restrict__ out) {
    __shared__ float2 sm[WARPS_PER_BLOCK][512];

    const int t  = threadIdx.x & 31;                    // lane = n2
    const int wi = threadIdx.x >> 5;                    // warp = FFT slot
    const int f  = blockIdx.x * WARPS_PER_BLOCK + wi;   // global FFT index (2 rows)

    const float* __restrict__ A = x + (size_t)(2 * f) * 512;
    const float* __restrict__ B = A + 512;
    float2* s = sm[wi];

    // Load + window: reg j holds z[32j + t]
    float2 r[16];
    #pragma unroll
    for (int j = 0; j < 16; j++) {
        int n  = 32 * j + t;
        float wv = __ldg(win + n);
        r[j] = make_float2(__ldg(A + n) * wv, __ldg(B + n) * wv);
    }

    // ---- Stage A: radix-16 over regs (n1), then twiddle W512^(t*k1) ----
    fft16(r);
    {
        float sn, cs;
        __sincosf((-6.2831853071795864769f / 512.0f) * (float)t, &sn, &cs);
        float2 wb = make_float2(cs, sn);
        float2 wk = wb;
        r[1] = cmul(r[1], wk);
        #pragma unroll
        for (int k = 2; k < 16; k++) { wk = cmul(wk, wb); r[k] = cmul(r[k], wk); }
    }

    // ---- Stage B: radix-2 across lanes (xor 16); odd half gets W32^(t&15) ----
    {
        float sn, cs;
        __sincosf((-6.2831853071795864769f / 32.0f) * (float)(t & 15), &sn, &cs);
        const float sgn = (t < 16) ? 1.0f : -1.0f;
        const float2 wb = (t < 16) ? make_float2(1.0f, 0.0f) : make_float2(cs, sn);
        #pragma unroll
        for (int k = 0; k < 16; k++) {
            float ox = __shfl_xor_sync(FULLM, r[k].x, 16);
            float oy = __shfl_xor_sync(FULLM, r[k].y, 16);
            // lower: mine + other ; upper: other - mine  (== ox + sgn*mine)
            float2 v = make_float2(fmaf(sgn, r[k].x, ox), fmaf(sgn, r[k].y, oy));
            r[k] = cmul(v, wb);
        }
    }

    // ---- Stage C: single smem exchange, XOR-swizzled (conflict-free) ----
    // logical write pos: v = 32*k1 + t  (t = 16*par + n2'); phys = v ^ ((v>>5)&15) = 32k + (t^k)
    #pragma unroll
    for (int k = 0; k < 16; k++) s[32 * k + (t ^ k)] = r[k];
    __syncwarp();
    {
        const int m = t & 15, h = t >> 4;      // this thread owns (k1=m, par=h)
        const int base = 32 * m + 16 * h;
        #pragma unroll
        for (int j = 0; j < 16; j++) r[j] = s[base - 16 * h + ((16 * h + j) ^ m)];
    }

    // ---- Stage D: final radix-16 over regs -> r[k] = X[t + 32k] ----
    fft16(r);

    // ---- Hermitian split + mirror via intra-warp shuffle, aligned stores ----
    // X[512-K] for K = t+32k lives at lane (32-t)&31, reg 15-k  (t>=1);
    // lane 0 self-pairs: reg (16-k)&15.
    float* __restrict__ outA = out + (size_t)(2 * f) * 512;
    float* __restrict__ outB = outA + 512;
    const int src = (32 - t) & 31;
    #pragma unroll
    for (int k = 0; k < 16; k++) {
        float px = __shfl_sync(FULLM, r[15 - k].x, src);
        float py = __shfl_sync(FULLM, r[15 - k].y, src);
        if (t == 0) { px = r[(16 - k) & 15].x; py = r[(16 - k) & 15].y; }
        int K = t + 32 * k;
        outA[K] = 0.5f * (r[k].x + px);   // Re FFT(a)[K]  (even-symmetric)
        outB[K] = 0.5f * (r[k].y + py);   // Re FFT(b)[K]
    }
}

extern "C" void kernel_launch(void* const* d_in, const int* in_sizes, int n_in,
                              void* d_out, int out_size) {
    const float* x   = (const float*)d_in[0];   // (256,256,512) fp32
    const float* win = (const float*)d_in[1];   // (512,) fp32
    float* out = (float*)d_out;                 // (256,256,512,1) fp32

    int rows   = in_sizes[0] / 512;             // 65536
    int nffts  = rows >> 1;                     // 32768
    int blocks = nffts / WARPS_PER_BLOCK;       // 8192

    fft512_warp_kernel<<<blocks, NTHREADS>>>(x, win, out);
}